// round 15
// baseline (speedup 1.0000x reference)
#include <cuda_runtime.h>
#include <cstdint>

// Problem dims
#define N_B   64
#define I_DIM 256
#define H_DIM 1024
#define O_DIM 18
#define T_DIM 500
#define PAIRS (N_B * T_DIM)          // 32000 (n,t) pairs

// Recurrence constants
#define D1 0.9048374180359595f       // exp(-1/10)
#define C1 0.2718281828459045f       // e/10
#define D2 0.36787944117144233f      // exp(-1)
#define C2 2.718281828459045f        // e
#define THETA 10.0f
#define REFSCALE -20.0f              // -scaleRef*theta

// ---- scratch (static device arrays) ----
__device__ float g_W1t[(size_t)I_DIM * H_DIM];         // W1 transposed [i][h]
__device__ float g_W2t[(size_t)H_DIM * O_DIM];         // W2 transposed [h][o]
__device__ float g_y1[(size_t)PAIRS * H_DIM];          // layer-1 pre-psp
__device__ unsigned int g_smask[(size_t)PAIRS * 32];   // s1 spike bitmask [m][h/32]
__device__ float g_y2[(size_t)PAIRS * O_DIM];          // layer-2 pre-psp
__device__ int g_listi[(size_t)PAIRS * 256];           // active idx<<8 (float4-row offsets), EXACT count
__device__ int g_counts[PAIRS];

// ---------------------------------------------------------------------------
// Kernel 1: build per-(n,t) active-input lists via warp-parallel ballots.
// ---------------------------------------------------------------------------
__global__ void build_lists(const float* __restrict__ spike) {
    __shared__ float flags[I_DIM][33];
    int n  = blockIdx.x;
    int t0 = blockIdx.y * 32;
    int tid = threadIdx.x;
    int tl  = tid & 31;
    int w   = tid >> 5;              // warp 0..7

    #pragma unroll 4
    for (int ic = 0; ic < 32; ic++) {
        int i = ic * 8 + w;
        int t = t0 + tl;
        float v = 0.f;
        if (t < T_DIM) v = spike[((size_t)(n * I_DIM + i)) * T_DIM + t];
        flags[i][tl] = v;
    }
    __syncthreads();

    unsigned int ltmask = (1u << tl) - 1u;
    for (int tt = 0; tt < 4; tt++) {
        int tloc = w * 4 + tt;
        int t = t0 + tloc;
        if (t >= T_DIM) continue;
        int m = n * T_DIM + t;
        int* lp = g_listi + (size_t)m * 256;
        int base = 0;
        #pragma unroll
        for (int chunk = 0; chunk < 8; chunk++) {
            float v = flags[chunk * 32 + tl][tloc];
            unsigned int bal = __ballot_sync(0xffffffffu, v != 0.f);
            if (v != 0.f) lp[base + __popc(bal & ltmask)] = (chunk * 32 + tl) << 8;
            base += __popc(bal);
        }
        if (tl == 0) g_counts[m] = base;
    }
}

// ---------------------------------------------------------------------------
// Kernel 2: transpose W1 [H][I] -> W1t [I][H]; extra y-blocks handle W2 -> W2t.
// ---------------------------------------------------------------------------
__global__ void transpose_w(const float* __restrict__ W1,
                            const float* __restrict__ W2) {
    if (blockIdx.y < H_DIM / 32) {
        __shared__ float tile[32][33];
        int i0 = blockIdx.x * 32;
        int h0 = blockIdx.y * 32;
        int tx = threadIdx.x, ty = threadIdx.y;   // (32, 8)
        #pragma unroll
        for (int r = 0; r < 32; r += 8)
            tile[ty + r][tx] = W1[(size_t)(h0 + ty + r) * I_DIM + i0 + tx];
        __syncthreads();
        #pragma unroll
        for (int r = 0; r < 32; r += 8)
            g_W1t[(size_t)(i0 + ty + r) * H_DIM + h0 + tx] = tile[tx][ty + r];
    } else {
        int idx = (blockIdx.x + (blockIdx.y - H_DIM / 32) * gridDim.x) * 256
                  + threadIdx.y * 32 + threadIdx.x;
        if (idx < O_DIM * H_DIM) {
            int o = idx / H_DIM;
            int h = idx - o * H_DIM;
            g_W2t[(size_t)h * O_DIM + o] = W2[idx];
        }
    }
}

// ---------------------------------------------------------------------------
// Kernel 3: sparse GEMM1 (unchanged from best config). Warp per m,
// 32 lanes x float4 = 128 h; MLP=4 batches + scalar tail, exact counts.
// ---------------------------------------------------------------------------
__global__ void gather_y1() {
    int warp = threadIdx.x >> 5;
    int lane = threadIdx.x & 31;
    int h4   = blockIdx.y * 32 + lane;
    const float4* __restrict__ Wt = (const float4*)g_W1t;
    int m0 = blockIdx.x * 64;

    for (int k = 0; k < 8; k++) {
        int m = m0 + warp * 8 + k;
        int cnt = g_counts[m];
        const int* lp = g_listi + (size_t)m * 256;
        float4 acc = make_float4(0.f, 0.f, 0.f, 0.f);
        int j = 0;
        for (; j + 4 <= cnt; j += 4) {
            int4 u = *(const int4*)(lp + j);
            float4 a = Wt[u.x + h4];
            float4 b = Wt[u.y + h4];
            float4 c = Wt[u.z + h4];
            float4 d = Wt[u.w + h4];
            acc.x += a.x; acc.x += b.x; acc.x += c.x; acc.x += d.x;
            acc.y += a.y; acc.y += b.y; acc.y += c.y; acc.y += d.y;
            acc.z += a.z; acc.z += b.z; acc.z += c.z; acc.z += d.z;
            acc.w += a.w; acc.w += b.w; acc.w += c.w; acc.w += d.w;
        }
        for (; j < cnt; j++) {
            float4 a = Wt[lp[j] + h4];
            acc.x += a.x; acc.y += a.y; acc.z += a.z; acc.w += a.w;
        }
        ((float4*)g_y1)[(size_t)m * (H_DIM / 4) + h4] = acc;
    }
}

// ---------------------------------------------------------------------------
// Kernel 4: fused psp + spike scan, layer 1. Double-buffered prefetch:
// batch t+1 loads issue BEFORE batch t's compute -> loads always in flight.
// ---------------------------------------------------------------------------
__global__ void scan_layer1() {
    int n = blockIdx.x >> 2;
    int h = ((blockIdx.x & 3) << 8) + threadIdx.x;
    int lane = threadIdx.x & 31;
    const float* __restrict__ yp = g_y1 + (size_t)n * T_DIM * H_DIM + h;
    unsigned int* mp = g_smask + (size_t)n * T_DIM * 32 + (h >> 5);

    float p1 = 0.f, a1 = 0.f, p2 = 0.f, a2 = 0.f;
    float cur[20], nxt[20];
    #pragma unroll
    for (int k = 0; k < 20; k++) cur[k] = yp[(size_t)k * H_DIM];

    for (int t = 0; t < T_DIM; t += 20) {
        if (t + 20 < T_DIM) {
            #pragma unroll
            for (int k = 0; k < 20; k++)
                nxt[k] = yp[(size_t)(t + 20 + k) * H_DIM];
        }
        #pragma unroll
        for (int k = 0; k < 20; k++) {
            a1 = D1 * (a1 + p1);
            p1 = D1 * p1 + cur[k];
            a2 = D2 * (a2 + p2);
            float u = C1 * a1 + C2 * a2;
            float s = (u - THETA >= 0.f) ? 1.0f : 0.0f;
            p2 = D2 * p2 + REFSCALE * s;
            unsigned int bal = __ballot_sync(0xffffffffu, s != 0.f);
            if (lane == 0) mp[(size_t)(t + k) * 32] = bal;
        }
        #pragma unroll
        for (int k = 0; k < 20; k++) cur[k] = nxt[k];
    }
}

// ---------------------------------------------------------------------------
// Kernel 5: bit-sparse GEMM2 with W2t staged in 72KB smem (LDS inner loop).
// Block = 64 m (8 warps x 8 m, processed in interleaved pairs).
// ---------------------------------------------------------------------------
__global__ void gemm2_sparse() {
    extern __shared__ float sW2[];                   // [H_DIM][O_DIM] = 72KB
    int tid  = threadIdx.x;
    int warp = tid >> 5;
    int lane = tid & 31;

    #pragma unroll
    for (int j = 0; j < (H_DIM * O_DIM) / 256; j++)
        sW2[j * 256 + tid] = g_W2t[j * 256 + tid];
    __syncthreads();

    int m0 = blockIdx.x * 64 + warp * 8;
    bool act = (lane < O_DIM);

    for (int k = 0; k < 8; k += 2) {
        int m = m0 + k;
        unsigned int wA = g_smask[(size_t)m * 32 + lane];
        unsigned int wB = g_smask[(size_t)(m + 1) * 32 + lane];
        float accA = 0.f, accB = 0.f;

        #pragma unroll 4
        for (int src = 0; src < 32; src++) {
            unsigned int a = __shfl_sync(0xffffffffu, wA, src);
            unsigned int b = __shfl_sync(0xffffffffu, wB, src);
            int hb = src << 5;
            while (a | b) {
                if (a) {
                    int bit = __ffs(a) - 1; a &= a - 1;
                    if (act) accA += sW2[(hb + bit) * O_DIM + lane];
                }
                if (b) {
                    int bit = __ffs(b) - 1; b &= b - 1;
                    if (act) accB += sW2[(hb + bit) * O_DIM + lane];
                }
            }
        }
        if (act) {
            g_y2[(size_t)m * O_DIM + lane] = accA;
            g_y2[(size_t)(m + 1) * O_DIM + lane] = accB;
        }
    }
}

// ---------------------------------------------------------------------------
// Kernel 6: fused psp + spike scan, layer 2. Double-buffered. Out [n][o][t].
// ---------------------------------------------------------------------------
__global__ void scan_layer2(float* __restrict__ out) {
    int idx = blockIdx.x * blockDim.x + threadIdx.x;
    if (idx >= N_B * O_DIM) return;
    int n = idx / O_DIM;
    int o = idx - n * O_DIM;
    const float* __restrict__ yp = g_y2 + (size_t)n * T_DIM * O_DIM + o;
    float*       op = out + (size_t)idx * T_DIM;

    float p1 = 0.f, a1 = 0.f, p2 = 0.f, a2 = 0.f;
    float cur[20], nxt[20];
    #pragma unroll
    for (int k = 0; k < 20; k++) cur[k] = yp[(size_t)k * O_DIM];

    for (int t = 0; t < T_DIM; t += 20) {
        if (t + 20 < T_DIM) {
            #pragma unroll
            for (int k = 0; k < 20; k++)
                nxt[k] = yp[(size_t)(t + 20 + k) * O_DIM];
        }
        #pragma unroll
        for (int k = 0; k < 20; k++) {
            a1 = D1 * (a1 + p1);
            p1 = D1 * p1 + cur[k];
            a2 = D2 * (a2 + p2);
            float u = C1 * a1 + C2 * a2;
            float s = (u - THETA >= 0.f) ? 1.0f : 0.0f;
            p2 = D2 * p2 + REFSCALE * s;
            op[t + k] = s;
        }
        #pragma unroll
        for (int k = 0; k < 20; k++) cur[k] = nxt[k];
    }
}

// ---------------------------------------------------------------------------
extern "C" void kernel_launch(void* const* d_in, const int* in_sizes, int n_in,
                              void* d_out, int out_size) {
    const float* spike = (const float*)d_in[0];   // [64][256][500]
    const float* W1    = (const float*)d_in[1];   // [1024][256]
    const float* W2    = (const float*)d_in[2];   // [18][1024]
    float* out = (float*)d_out;                   // [64][18][500]

    static int smem_set = 0;
    if (!smem_set) {
        cudaFuncSetAttribute(gemm2_sparse,
                             cudaFuncAttributeMaxDynamicSharedMemorySize,
                             H_DIM * O_DIM * sizeof(float));
        smem_set = 1;
    }

    build_lists<<<dim3(N_B, 16), 256>>>(spike);
    transpose_w<<<dim3(I_DIM / 32, H_DIM / 32 + 9), dim3(32, 8)>>>(W1, W2);
    gather_y1<<<dim3(500, 8), 256>>>();
    scan_layer1<<<256, 256>>>();
    gemm2_sparse<<<PAIRS / 64, 256, H_DIM * O_DIM * sizeof(float)>>>();
    scan_layer2<<<5, 256>>>(out);
}

// round 16
// speedup vs baseline: 1.0524x; 1.0524x over previous
#include <cuda_runtime.h>
#include <cstdint>

// Problem dims
#define N_B   64
#define I_DIM 256
#define H_DIM 1024
#define O_DIM 18
#define T_DIM 500
#define PAIRS (N_B * T_DIM)          // 32000 (n,t) pairs

// Recurrence constants
#define D1 0.9048374180359595f       // exp(-1/10)
#define C1 0.2718281828459045f       // e/10
#define D2 0.36787944117144233f      // exp(-1)
#define C2 2.718281828459045f        // e
#define THETA 10.0f
#define REFSCALE -20.0f              // -scaleRef*theta

// ---- scratch (static device arrays) ----
__device__ float g_W1t[(size_t)I_DIM * H_DIM];         // W1 transposed [i][h]
__device__ float g_W2t[(size_t)H_DIM * O_DIM];         // W2 transposed [h][o]
__device__ float g_y1[(size_t)PAIRS * H_DIM];          // layer-1 pre-psp
__device__ unsigned int g_smask[(size_t)PAIRS * 32];   // s1 spike bitmask [m][h/32]
__device__ float g_y2[(size_t)PAIRS * O_DIM];          // layer-2 pre-psp
__device__ int g_listi[(size_t)PAIRS * 256];           // active idx<<8 (float4-row offsets), EXACT count
__device__ int g_counts[PAIRS];

// ---------------------------------------------------------------------------
// Kernel 1: build per-(n,t) active-input lists via warp-parallel ballots.
// ---------------------------------------------------------------------------
__global__ void build_lists(const float* __restrict__ spike) {
    __shared__ float flags[I_DIM][33];
    int n  = blockIdx.x;
    int t0 = blockIdx.y * 32;
    int tid = threadIdx.x;
    int tl  = tid & 31;
    int w   = tid >> 5;              // warp 0..7

    #pragma unroll 4
    for (int ic = 0; ic < 32; ic++) {
        int i = ic * 8 + w;
        int t = t0 + tl;
        float v = 0.f;
        if (t < T_DIM) v = spike[((size_t)(n * I_DIM + i)) * T_DIM + t];
        flags[i][tl] = v;
    }
    __syncthreads();

    unsigned int ltmask = (1u << tl) - 1u;
    for (int tt = 0; tt < 4; tt++) {
        int tloc = w * 4 + tt;
        int t = t0 + tloc;
        if (t >= T_DIM) continue;
        int m = n * T_DIM + t;
        int* lp = g_listi + (size_t)m * 256;
        int base = 0;
        #pragma unroll
        for (int chunk = 0; chunk < 8; chunk++) {
            float v = flags[chunk * 32 + tl][tloc];
            unsigned int bal = __ballot_sync(0xffffffffu, v != 0.f);
            if (v != 0.f) lp[base + __popc(bal & ltmask)] = (chunk * 32 + tl) << 8;
            base += __popc(bal);
        }
        if (tl == 0) g_counts[m] = base;
    }
}

// ---------------------------------------------------------------------------
// Kernel 2: transpose W1 [H][I] -> W1t [I][H]; extra y-blocks handle W2 -> W2t.
// ---------------------------------------------------------------------------
__global__ void transpose_w(const float* __restrict__ W1,
                            const float* __restrict__ W2) {
    if (blockIdx.y < H_DIM / 32) {
        __shared__ float tile[32][33];
        int i0 = blockIdx.x * 32;
        int h0 = blockIdx.y * 32;
        int tx = threadIdx.x, ty = threadIdx.y;   // (32, 8)
        #pragma unroll
        for (int r = 0; r < 32; r += 8)
            tile[ty + r][tx] = W1[(size_t)(h0 + ty + r) * I_DIM + i0 + tx];
        __syncthreads();
        #pragma unroll
        for (int r = 0; r < 32; r += 8)
            g_W1t[(size_t)(i0 + ty + r) * H_DIM + h0 + tx] = tile[tx][ty + r];
    } else {
        int idx = (blockIdx.x + (blockIdx.y - H_DIM / 32) * gridDim.x) * 256
                  + threadIdx.y * 32 + threadIdx.x;
        if (idx < O_DIM * H_DIM) {
            int o = idx / H_DIM;
            int h = idx - o * H_DIM;
            g_W2t[(size_t)h * O_DIM + o] = W2[idx];
        }
    }
}

// ---------------------------------------------------------------------------
// Kernel 3: sparse GEMM1 (best known config — do not touch). Warp per m,
// 32 lanes x float4 = 128 h; MLP=4 batches + scalar tail, exact counts.
// ---------------------------------------------------------------------------
__global__ void gather_y1() {
    int warp = threadIdx.x >> 5;
    int lane = threadIdx.x & 31;
    int h4   = blockIdx.y * 32 + lane;
    const float4* __restrict__ Wt = (const float4*)g_W1t;
    int m0 = blockIdx.x * 64;

    for (int k = 0; k < 8; k++) {
        int m = m0 + warp * 8 + k;
        int cnt = g_counts[m];
        const int* lp = g_listi + (size_t)m * 256;
        float4 acc = make_float4(0.f, 0.f, 0.f, 0.f);
        int j = 0;
        for (; j + 4 <= cnt; j += 4) {
            int4 u = *(const int4*)(lp + j);
            float4 a = Wt[u.x + h4];
            float4 b = Wt[u.y + h4];
            float4 c = Wt[u.z + h4];
            float4 d = Wt[u.w + h4];
            acc.x += a.x; acc.x += b.x; acc.x += c.x; acc.x += d.x;
            acc.y += a.y; acc.y += b.y; acc.y += c.y; acc.y += d.y;
            acc.z += a.z; acc.z += b.z; acc.z += c.z; acc.z += d.z;
            acc.w += a.w; acc.w += b.w; acc.w += c.w; acc.w += d.w;
        }
        for (; j < cnt; j++) {
            float4 a = Wt[lp[j] + h4];
            acc.x += a.x; acc.y += a.y; acc.z += a.z; acc.w += a.w;
        }
        ((float4*)g_y1)[(size_t)m * (H_DIM / 4) + h4] = acc;
    }
}

// ---------------------------------------------------------------------------
// Kernel 4: fused psp + spike scan, layer 1. Double-buffered prefetch.
// ---------------------------------------------------------------------------
__global__ void scan_layer1() {
    int n = blockIdx.x >> 2;
    int h = ((blockIdx.x & 3) << 8) + threadIdx.x;
    int lane = threadIdx.x & 31;
    const float* __restrict__ yp = g_y1 + (size_t)n * T_DIM * H_DIM + h;
    unsigned int* mp = g_smask + (size_t)n * T_DIM * 32 + (h >> 5);

    float p1 = 0.f, a1 = 0.f, p2 = 0.f, a2 = 0.f;
    float cur[20], nxt[20];
    #pragma unroll
    for (int k = 0; k < 20; k++) cur[k] = yp[(size_t)k * H_DIM];

    for (int t = 0; t < T_DIM; t += 20) {
        if (t + 20 < T_DIM) {
            #pragma unroll
            for (int k = 0; k < 20; k++)
                nxt[k] = yp[(size_t)(t + 20 + k) * H_DIM];
        }
        #pragma unroll
        for (int k = 0; k < 20; k++) {
            a1 = D1 * (a1 + p1);
            p1 = D1 * p1 + cur[k];
            a2 = D2 * (a2 + p2);
            float u = C1 * a1 + C2 * a2;
            float s = (u - THETA >= 0.f) ? 1.0f : 0.0f;
            p2 = D2 * p2 + REFSCALE * s;
            unsigned int bal = __ballot_sync(0xffffffffu, s != 0.f);
            if (lane == 0) mp[(size_t)(t + k) * 32] = bal;
        }
        #pragma unroll
        for (int k = 0; k < 20; k++) cur[k] = nxt[k];
    }
}

// ---------------------------------------------------------------------------
// Kernel 5: bit-sparse GEMM2, global-L1 W2t, FOUR interleaved m per warp
// (4 independent ffs/load chains hide L1-hit latency). Lanes 0..17 own o.
// Per-m ascending-h add order (bit-exact vs previous passing kernels).
// ---------------------------------------------------------------------------
__global__ void gemm2_sparse() {
    int warp = threadIdx.x >> 5;
    int lane = threadIdx.x & 31;
    int m = blockIdx.x * 32 + warp * 4;       // four m per warp

    unsigned int wA = g_smask[(size_t)m * 32 + lane];
    unsigned int wB = g_smask[(size_t)(m + 1) * 32 + lane];
    unsigned int wC = g_smask[(size_t)(m + 2) * 32 + lane];
    unsigned int wD = g_smask[(size_t)(m + 3) * 32 + lane];
    float accA = 0.f, accB = 0.f, accC = 0.f, accD = 0.f;
    bool act = (lane < O_DIM);
    const float* __restrict__ W2t = g_W2t;

    #pragma unroll 4
    for (int src = 0; src < 32; src++) {
        unsigned int a = __shfl_sync(0xffffffffu, wA, src);
        unsigned int b = __shfl_sync(0xffffffffu, wB, src);
        unsigned int c = __shfl_sync(0xffffffffu, wC, src);
        unsigned int d = __shfl_sync(0xffffffffu, wD, src);
        int hb = src << 5;
        while (a | b | c | d) {
            if (a) {
                int bit = __ffs(a) - 1; a &= a - 1;
                if (act) accA += W2t[(hb + bit) * O_DIM + lane];
            }
            if (b) {
                int bit = __ffs(b) - 1; b &= b - 1;
                if (act) accB += W2t[(hb + bit) * O_DIM + lane];
            }
            if (c) {
                int bit = __ffs(c) - 1; c &= c - 1;
                if (act) accC += W2t[(hb + bit) * O_DIM + lane];
            }
            if (d) {
                int bit = __ffs(d) - 1; d &= d - 1;
                if (act) accD += W2t[(hb + bit) * O_DIM + lane];
            }
        }
    }
    if (act) {
        g_y2[(size_t)m * O_DIM + lane]       = accA;
        g_y2[(size_t)(m + 1) * O_DIM + lane] = accB;
        g_y2[(size_t)(m + 2) * O_DIM + lane] = accC;
        g_y2[(size_t)(m + 3) * O_DIM + lane] = accD;
    }
}

// ---------------------------------------------------------------------------
// Kernel 6: fused psp + spike scan, layer 2. Double-buffered. Out [n][o][t].
// ---------------------------------------------------------------------------
__global__ void scan_layer2(float* __restrict__ out) {
    int idx = blockIdx.x * blockDim.x + threadIdx.x;
    if (idx >= N_B * O_DIM) return;
    int n = idx / O_DIM;
    int o = idx - n * O_DIM;
    const float* __restrict__ yp = g_y2 + (size_t)n * T_DIM * O_DIM + o;
    float*       op = out + (size_t)idx * T_DIM;

    float p1 = 0.f, a1 = 0.f, p2 = 0.f, a2 = 0.f;
    float cur[20], nxt[20];
    #pragma unroll
    for (int k = 0; k < 20; k++) cur[k] = yp[(size_t)k * O_DIM];

    for (int t = 0; t < T_DIM; t += 20) {
        if (t + 20 < T_DIM) {
            #pragma unroll
            for (int k = 0; k < 20; k++)
                nxt[k] = yp[(size_t)(t + 20 + k) * O_DIM];
        }
        #pragma unroll
        for (int k = 0; k < 20; k++) {
            a1 = D1 * (a1 + p1);
            p1 = D1 * p1 + cur[k];
            a2 = D2 * (a2 + p2);
            float u = C1 * a1 + C2 * a2;
            float s = (u - THETA >= 0.f) ? 1.0f : 0.0f;
            p2 = D2 * p2 + REFSCALE * s;
            op[t + k] = s;
        }
        #pragma unroll
        for (int k = 0; k < 20; k++) cur[k] = nxt[k];
    }
}

// ---------------------------------------------------------------------------
extern "C" void kernel_launch(void* const* d_in, const int* in_sizes, int n_in,
                              void* d_out, int out_size) {
    const float* spike = (const float*)d_in[0];   // [64][256][500]
    const float* W1    = (const float*)d_in[1];   // [1024][256]
    const float* W2    = (const float*)d_in[2];   // [18][1024]
    float* out = (float*)d_out;                   // [64][18][500]

    build_lists<<<dim3(N_B, 16), 256>>>(spike);
    transpose_w<<<dim3(I_DIM / 32, H_DIM / 32 + 9), dim3(32, 8)>>>(W1, W2);
    gather_y1<<<dim3(500, 8), 256>>>();
    scan_layer1<<<256, 256>>>();
    gemm2_sparse<<<PAIRS / 32, 256>>>();
    scan_layer2<<<5, 256>>>(out);
}

// round 17
// speedup vs baseline: 1.0603x; 1.0075x over previous
#include <cuda_runtime.h>
#include <cstdint>

// Problem dims
#define N_B   64
#define I_DIM 256
#define H_DIM 1024
#define O_DIM 18
#define T_DIM 500
#define PAIRS (N_B * T_DIM)          // 32000 (n,t) pairs

// Recurrence constants
#define D1 0.9048374180359595f       // exp(-1/10)
#define C1 0.2718281828459045f       // e/10
#define D2 0.36787944117144233f      // exp(-1)
#define C2 2.718281828459045f        // e
#define THETA 10.0f
#define REFSCALE -20.0f              // -scaleRef*theta

// ---- scratch (static device arrays) ----
__device__ float g_W1t[(size_t)I_DIM * H_DIM];         // W1 transposed [i][h]
__device__ float g_W2t[(size_t)H_DIM * O_DIM];         // W2 transposed [h][o]
__device__ float g_y1[(size_t)PAIRS * H_DIM];          // layer-1 pre-psp
__device__ unsigned int g_smask[(size_t)PAIRS * 32];   // s1 spike bitmask [m][h/32]
__device__ float g_y2[(size_t)PAIRS * O_DIM];          // layer-2 pre-psp
__device__ int g_listi[(size_t)PAIRS * 256];           // active idx<<8 (float4-row offsets), EXACT count
__device__ int g_counts[PAIRS];

// ---------------------------------------------------------------------------
// Kernel 1: build active-input lists (warp-parallel ballots). Extra grid
// y-slice (blockIdx.y == 16) performs both weight transposes.
// ---------------------------------------------------------------------------
__global__ void build_lists(const float* __restrict__ spike,
                            const float* __restrict__ W1,
                            const float* __restrict__ W2) {
    if (blockIdx.y == 16) {
        // 64 blocks x 256 threads handle W1 (262144) + W2 (18432) transposes.
        int g = blockIdx.x * 256 + threadIdx.x;     // 0..16383
        #pragma unroll
        for (int r = 0; r < 16; r++) {
            int idx = g + r * 16384;                // over W1t element space
            int i = idx >> 10;                      // W1t[i][h]
            int h = idx & 1023;
            g_W1t[idx] = W1[h * I_DIM + i];
        }
        if (g < O_DIM * H_DIM) {
            int o = g / H_DIM;
            int h = g - o * H_DIM;
            g_W2t[h * O_DIM + o] = W2[g];
        }
        if (g + 16384 < O_DIM * H_DIM) {
            int idx = g + 16384;
            int o = idx / H_DIM;
            int h = idx - o * H_DIM;
            g_W2t[h * O_DIM + o] = W2[idx];
        }
        return;
    }

    __shared__ float flags[I_DIM][33];
    int n  = blockIdx.x;
    int t0 = blockIdx.y * 32;
    int tid = threadIdx.x;
    int tl  = tid & 31;
    int w   = tid >> 5;              // warp 0..7

    #pragma unroll 4
    for (int ic = 0; ic < 32; ic++) {
        int i = ic * 8 + w;
        int t = t0 + tl;
        float v = 0.f;
        if (t < T_DIM) v = spike[((size_t)(n * I_DIM + i)) * T_DIM + t];
        flags[i][tl] = v;
    }
    __syncthreads();

    unsigned int ltmask = (1u << tl) - 1u;
    for (int tt = 0; tt < 4; tt++) {
        int tloc = w * 4 + tt;
        int t = t0 + tloc;
        if (t >= T_DIM) continue;
        int m = n * T_DIM + t;
        int* lp = g_listi + (size_t)m * 256;
        int base = 0;
        #pragma unroll
        for (int chunk = 0; chunk < 8; chunk++) {
            float v = flags[chunk * 32 + tl][tloc];
            unsigned int bal = __ballot_sync(0xffffffffu, v != 0.f);
            if (v != 0.f) lp[base + __popc(bal & ltmask)] = (chunk * 32 + tl) << 8;
            base += __popc(bal);
        }
        if (tl == 0) g_counts[m] = base;
    }
}

// ---------------------------------------------------------------------------
// Kernel 2: sparse GEMM1. Warp per m, TWO h-tiles per warp (h4 and h4+32):
// 8 independent LDG.128 in flight per 4-index batch, halved list overhead.
// Per-(m,h) add order identical to prior passing kernels.
// ---------------------------------------------------------------------------
__global__ void gather_y1() {
    int warp = threadIdx.x >> 5;
    int lane = threadIdx.x & 31;
    int h4a  = blockIdx.y * 64 + lane;        // float4 column, tile A
    int h4b  = h4a + 32;                      // float4 column, tile B
    const float4* __restrict__ Wt = (const float4*)g_W1t;
    int m0 = blockIdx.x * 64;

    for (int k = 0; k < 8; k++) {
        int m = m0 + warp * 8 + k;
        int cnt = g_counts[m];
        const int* lp = g_listi + (size_t)m * 256;
        float4 accA = make_float4(0.f, 0.f, 0.f, 0.f);
        float4 accB = make_float4(0.f, 0.f, 0.f, 0.f);
        int j = 0;
        for (; j + 4 <= cnt; j += 4) {
            int4 u = *(const int4*)(lp + j);
            float4 a0 = Wt[u.x + h4a];
            float4 b0 = Wt[u.x + h4b];
            float4 a1 = Wt[u.y + h4a];
            float4 b1 = Wt[u.y + h4b];
            float4 a2 = Wt[u.z + h4a];
            float4 b2 = Wt[u.z + h4b];
            float4 a3 = Wt[u.w + h4a];
            float4 b3 = Wt[u.w + h4b];
            accA.x += a0.x; accA.x += a1.x; accA.x += a2.x; accA.x += a3.x;
            accA.y += a0.y; accA.y += a1.y; accA.y += a2.y; accA.y += a3.y;
            accA.z += a0.z; accA.z += a1.z; accA.z += a2.z; accA.z += a3.z;
            accA.w += a0.w; accA.w += a1.w; accA.w += a2.w; accA.w += a3.w;
            accB.x += b0.x; accB.x += b1.x; accB.x += b2.x; accB.x += b3.x;
            accB.y += b0.y; accB.y += b1.y; accB.y += b2.y; accB.y += b3.y;
            accB.z += b0.z; accB.z += b1.z; accB.z += b2.z; accB.z += b3.z;
            accB.w += b0.w; accB.w += b1.w; accB.w += b2.w; accB.w += b3.w;
        }
        for (; j < cnt; j++) {
            int u = lp[j];
            float4 a = Wt[u + h4a];
            float4 b = Wt[u + h4b];
            accA.x += a.x; accA.y += a.y; accA.z += a.z; accA.w += a.w;
            accB.x += b.x; accB.y += b.y; accB.z += b.z; accB.w += b.w;
        }
        float4* dst = (float4*)g_y1 + (size_t)m * (H_DIM / 4);
        dst[h4a] = accA;
        dst[h4b] = accB;
    }
}

// ---------------------------------------------------------------------------
// Kernel 3: fused psp + spike scan, layer 1. Double-buffered prefetch.
// ---------------------------------------------------------------------------
__global__ void scan_layer1() {
    int n = blockIdx.x >> 2;
    int h = ((blockIdx.x & 3) << 8) + threadIdx.x;
    int lane = threadIdx.x & 31;
    const float* __restrict__ yp = g_y1 + (size_t)n * T_DIM * H_DIM + h;
    unsigned int* mp = g_smask + (size_t)n * T_DIM * 32 + (h >> 5);

    float p1 = 0.f, a1 = 0.f, p2 = 0.f, a2 = 0.f;
    float cur[20], nxt[20];
    #pragma unroll
    for (int k = 0; k < 20; k++) cur[k] = yp[(size_t)k * H_DIM];

    for (int t = 0; t < T_DIM; t += 20) {
        if (t + 20 < T_DIM) {
            #pragma unroll
            for (int k = 0; k < 20; k++)
                nxt[k] = yp[(size_t)(t + 20 + k) * H_DIM];
        }
        #pragma unroll
        for (int k = 0; k < 20; k++) {
            a1 = D1 * (a1 + p1);
            p1 = D1 * p1 + cur[k];
            a2 = D2 * (a2 + p2);
            float u = C1 * a1 + C2 * a2;
            float s = (u - THETA >= 0.f) ? 1.0f : 0.0f;
            p2 = D2 * p2 + REFSCALE * s;
            unsigned int bal = __ballot_sync(0xffffffffu, s != 0.f);
            if (lane == 0) mp[(size_t)(t + k) * 32] = bal;
        }
        #pragma unroll
        for (int k = 0; k < 20; k++) cur[k] = nxt[k];
    }
}

// ---------------------------------------------------------------------------
// Kernel 4: bit-sparse GEMM2, EIGHT interleaved m per warp (8 independent
// ffs/load chains fully hide L1-hit latency). Lanes 0..17 own output o.
// Per-m ascending-h add order (bit-exact vs previous passing kernels).
// ---------------------------------------------------------------------------
__global__ void gemm2_sparse() {
    int warp = threadIdx.x >> 5;
    int lane = threadIdx.x & 31;
    int m = blockIdx.x * 64 + warp * 8;       // eight m per warp

    unsigned int wm[8];
    float acc[8];
    #pragma unroll
    for (int q = 0; q < 8; q++) {
        wm[q] = g_smask[(size_t)(m + q) * 32 + lane];
        acc[q] = 0.f;
    }
    bool act = (lane < O_DIM);
    const float* __restrict__ W2t = g_W2t;

    for (int src = 0; src < 32; src++) {
        unsigned int b[8];
        #pragma unroll
        for (int q = 0; q < 8; q++) b[q] = __shfl_sync(0xffffffffu, wm[q], src);
        int hb = src << 5;
        unsigned int any = b[0] | b[1] | b[2] | b[3] | b[4] | b[5] | b[6] | b[7];
        while (any) {
            #pragma unroll
            for (int q = 0; q < 8; q++) {
                if (b[q]) {
                    int bit = __ffs(b[q]) - 1; b[q] &= b[q] - 1;
                    if (act) acc[q] += W2t[(hb + bit) * O_DIM + lane];
                }
            }
            any = b[0] | b[1] | b[2] | b[3] | b[4] | b[5] | b[6] | b[7];
        }
    }
    if (act) {
        #pragma unroll
        for (int q = 0; q < 8; q++)
            g_y2[(size_t)(m + q) * O_DIM + lane] = acc[q];
    }
}

// ---------------------------------------------------------------------------
// Kernel 5: fused psp + spike scan, layer 2. Double-buffered. Out [n][o][t].
// ---------------------------------------------------------------------------
__global__ void scan_layer2(float* __restrict__ out) {
    int idx = blockIdx.x * blockDim.x + threadIdx.x;
    if (idx >= N_B * O_DIM) return;
    int n = idx / O_DIM;
    int o = idx - n * O_DIM;
    const float* __restrict__ yp = g_y2 + (size_t)n * T_DIM * O_DIM + o;
    float*       op = out + (size_t)idx * T_DIM;

    float p1 = 0.f, a1 = 0.f, p2 = 0.f, a2 = 0.f;
    float cur[20], nxt[20];
    #pragma unroll
    for (int k = 0; k < 20; k++) cur[k] = yp[(size_t)k * O_DIM];

    for (int t = 0; t < T_DIM; t += 20) {
        if (t + 20 < T_DIM) {
            #pragma unroll
            for (int k = 0; k < 20; k++)
                nxt[k] = yp[(size_t)(t + 20 + k) * O_DIM];
        }
        #pragma unroll
        for (int k = 0; k < 20; k++) {
            a1 = D1 * (a1 + p1);
            p1 = D1 * p1 + cur[k];
            a2 = D2 * (a2 + p2);
            float u = C1 * a1 + C2 * a2;
            float s = (u - THETA >= 0.f) ? 1.0f : 0.0f;
            p2 = D2 * p2 + REFSCALE * s;
            op[t + k] = s;
        }
        #pragma unroll
        for (int k = 0; k < 20; k++) cur[k] = nxt[k];
    }
}

// ---------------------------------------------------------------------------
extern "C" void kernel_launch(void* const* d_in, const int* in_sizes, int n_in,
                              void* d_out, int out_size) {
    const float* spike = (const float*)d_in[0];   // [64][256][500]
    const float* W1    = (const float*)d_in[1];   // [1024][256]
    const float* W2    = (const float*)d_in[2];   // [18][1024]
    float* out = (float*)d_out;                   // [64][18][500]

    build_lists<<<dim3(N_B, 17), 256>>>(spike, W1, W2);
    gather_y1<<<dim3(500, 4), 256>>>();
    scan_layer1<<<256, 256>>>();
    gemm2_sparse<<<PAIRS / 64, 256>>>();
    scan_layer2<<<5, 256>>>(out);
}